// round 17
// baseline (speedup 1.0000x reference)
#include <cuda_runtime.h>
#include <cstdint>

#define SEQ   4096
#define HID   1280
#define NH    16
#define HD    80
#define HID3  3840
#define IMG_BLK 1024
#define ATT_SCALE 0.11180339887498949f  /* 80^-0.5 */

/* ------------ scratch (device globals: allocation-free rule) ------------- */
__device__ float    g_qkv[(size_t)SEQ * HID3];     /* qkv + bias (raw fp32)  */
__device__ uint32_t g_att[(size_t)SEQ * HID];      /* attn out, tf32-rounded */
__device__ uint32_t g_q[(size_t)NH * SEQ * HD];
__device__ uint32_t g_k[(size_t)NH * SEQ * HD];
__device__ uint32_t g_vt[(size_t)NH * HD * SEQ];   /* V transposed [h][d][s] */
__device__ uint32_t g_hid_r[(size_t)SEQ * HID];    /* rounded hidden         */
__device__ uint32_t g_wq_r[(size_t)HID3 * HID];    /* rounded qkv_w          */
__device__ uint32_t g_wp_r[(size_t)HID * HID];     /* rounded proj_w         */

/* ----------------------------- helpers ---------------------------------- */
__device__ __forceinline__ void cp_async16(void* smem, const void* gmem) {
    uint32_t s = (uint32_t)__cvta_generic_to_shared(smem);
    asm volatile("cp.async.cg.shared.global [%0], [%1], 16;\n" :: "r"(s), "l"(gmem));
}

/* mbarrier primitives (sm_80/90 PTX; compiles on bare compute_103) */
__device__ __forceinline__ void mbar_init(uint32_t mbar, uint32_t cnt) {
    asm volatile("mbarrier.init.shared.b64 [%0], %1;" :: "r"(mbar), "r"(cnt) : "memory");
}
__device__ __forceinline__ void mbar_arrive(uint32_t mbar) {
    asm volatile("mbarrier.arrive.shared.b64 _, [%0];" :: "r"(mbar) : "memory");
}
__device__ __forceinline__ void cpasync_arrive_noinc(uint32_t mbar) {
    asm volatile("cp.async.mbarrier.arrive.noinc.shared.b64 [%0];" :: "r"(mbar) : "memory");
}
__device__ __forceinline__ void mbar_wait(uint32_t mbar, uint32_t parity) {
    asm volatile(
        "{\n\t.reg .pred P;\n\t"
        "W_%=:\n\t"
        "mbarrier.try_wait.parity.acquire.cta.shared::cta.b64 P, [%0], %1, 0x989680;\n\t"
        "@P bra.uni D_%=;\n\t"
        "bra.uni W_%=;\n\t"
        "D_%=:\n\t}"
        :: "r"(mbar), "r"(parity) : "memory");
}

/* m16n8k8 tf32 mma, D += A*B (fp32 accum). Operands pre-rounded +0x1000. */
__device__ __forceinline__ void mma_tf32(float* d, const uint32_t* a, const uint32_t* b) {
    asm volatile(
        "mma.sync.aligned.m16n8k8.row.col.f32.tf32.tf32.f32 "
        "{%0,%1,%2,%3}, {%4,%5,%6,%7}, {%8,%9}, {%0,%1,%2,%3};\n"
        : "+f"(d[0]), "+f"(d[1]), "+f"(d[2]), "+f"(d[3])
        : "r"(a[0]), "r"(a[1]), "r"(a[2]), "r"(a[3]),
          "r"(b[0]), "r"(b[1]));
}

/* ldmatrix x4: four 8x8 b16 tiles (= 8 rows x 16B each) */
__device__ __forceinline__ void ldsm_x4(uint32_t* r, uint32_t saddr) {
    asm volatile(
        "ldmatrix.sync.aligned.m8n8.x4.shared.b16 {%0,%1,%2,%3}, [%4];\n"
        : "=r"(r[0]), "=r"(r[1]), "=r"(r[2]), "=r"(r[3]) : "r"(saddr));
}

/* ========== tf32 pre-round (fused): hidden + qkv_w + proj_w ============= */
#define RN1 (SEQ * HID / 4)
#define RN2 (RN1 + HID3 * HID / 4)
#define RN3 (RN2 + HID * HID / 4)
__global__ __launch_bounds__(256)
void round_all_kernel(const uint32_t* __restrict__ hid,
                      const uint32_t* __restrict__ wq,
                      const uint32_t* __restrict__ wp,
                      uint32_t* __restrict__ hid_r,
                      uint32_t* __restrict__ wq_r,
                      uint32_t* __restrict__ wp_r)
{
    int i = blockIdx.x * 256 + threadIdx.x;
    if (i >= RN3) return;
    const uint32_t* src;
    uint32_t* dst;
    int j;
    if (i < RN1)      { src = hid; dst = hid_r; j = i; }
    else if (i < RN2) { src = wq;  dst = wq_r;  j = i - RN1; }
    else              { src = wp;  dst = wp_r;  j = i - RN2; }
    uint4 v = ((const uint4*)src)[j];
    v.x += 0x1000u; v.y += 0x1000u; v.z += 0x1000u; v.w += 0x1000u;
    ((uint4*)dst)[j] = v;
}

/* ======================== GEMM: C = A * B^T + bias =======================
   128x128 tile, BK=16, ldmatrix frags, 5-stage cp.async mbarrier ring
   (deeper drift slack), free-running warps, 2 CTAs/SM. */
#define GBM 128
#define GBN 128
#define GBK 16
#define GPAD 20
#define GSTAGE 5
#define GS_U32  (2 * GBM * GPAD)
#define GS_BYTES (GS_U32 * 4)
#define GBAR_OFF (GSTAGE * GS_BYTES)          /* 102400 */
#define GEMM_SMEM (GBAR_OFF + 128)            /* 102528; x2 CTA = 205KB OK */

__global__ __launch_bounds__(256, 2)
void gemm_bias_kernel(const uint32_t* __restrict__ A, const uint32_t* __restrict__ B,
                      const float* __restrict__ bias, float* __restrict__ C,
                      int M, int N, int K)
{
    extern __shared__ uint32_t gsm[];
    const uint32_t sb = (uint32_t)__cvta_generic_to_shared(gsm);

    const int tid  = threadIdx.x;
    const int lane = tid & 31;
    const int warp = tid >> 5;
    const int wm   = (warp & 1) * 64;
    const int wn   = (warp >> 1) * 32;
    const int m0   = blockIdx.y * GBM;
    const int n0   = blockIdx.x * GBN;
    const int KT   = K / GBK;

    const int a_row = wm + ((lane >> 3) & 1) * 8 + (lane & 7);
    const int a_col = (lane >> 4) * 4;
    const int b_row = wn + ((lane >> 4) & 1) * 8 + (lane & 7);
    const int b_col = ((lane >> 3) & 1) * 4;

    /* full[5] at +0..40, empty[5] at +64..104 */
    const uint32_t fullb  = sb + GBAR_OFF;
    const uint32_t emptyb = sb + GBAR_OFF + 64;
    if (tid == 0) {
#pragma unroll
        for (int s = 0; s < GSTAGE; s++) {
            mbar_init(fullb  + s * 8, 256);
            mbar_init(emptyb + s * 8, 256);
        }
    }
    __syncthreads();

    float acc[4][4][4];
#pragma unroll
    for (int mt = 0; mt < 4; mt++)
#pragma unroll
        for (int nt = 0; nt < 4; nt++)
#pragma unroll
            for (int r = 0; r < 4; r++) acc[mt][nt][r] = 0.f;

    auto produce = [&](int kt, int s) {
        int k0 = kt * GBK;
        uint32_t* As = gsm + s * GS_U32;
        uint32_t* Bs = As + GBM * GPAD;
#pragma unroll
        for (int i = 0; i < 2; i++) {
            int f   = tid + i * 256;
            int row = f >> 2;
            int fc  = (f & 3) * 4;
            cp_async16(&As[row * GPAD + fc], &A[(size_t)(m0 + row) * K + k0 + fc]);
            cp_async16(&Bs[row * GPAD + fc], &B[(size_t)(n0 + row) * K + k0 + fc]);
        }
        cpasync_arrive_noinc(fullb + s * 8);
    };

    int fs = 0, fph = 0;
    int es = 0, eph = 1;

    /* prologue: fill GSTAGE-1 stages */
    for (int p0 = 0; p0 < GSTAGE - 1; p0++) {
        mbar_wait(emptyb + es * 8, eph);
        produce(p0, es);
        if (++es == GSTAGE) { es = 0; eph ^= 1; }
    }
    int pk = GSTAGE - 1;

#pragma unroll 1
    for (int kt = 0; kt < KT; kt++) {
        mbar_wait(fullb + fs * 8, fph);

        const uint32_t Ab = sb + fs * GS_BYTES;
        const uint32_t Bb = Ab + GBM * GPAD * 4;

#pragma unroll
        for (int ks = 0; ks < 2; ks++) {
            uint32_t a[4][4], b[2][4];
#pragma unroll
            for (int mt = 0; mt < 4; mt++)
                ldsm_x4(a[mt], Ab + (((a_row + mt * 16) * GPAD + a_col + ks * 8) << 2));
#pragma unroll
            for (int p = 0; p < 2; p++)
                ldsm_x4(b[p], Bb + (((b_row + p * 16) * GPAD + b_col + ks * 8) << 2));
#pragma unroll
            for (int mt = 0; mt < 4; mt++)
#pragma unroll
                for (int nt = 0; nt < 4; nt++)
                    mma_tf32(acc[mt][nt], a[mt], &b[nt >> 1][(nt & 1) * 2]);
        }

        mbar_arrive(emptyb + fs * 8);
        if (++fs == GSTAGE) { fs = 0; fph ^= 1; }

        if (pk < KT) {
            mbar_wait(emptyb + es * 8, eph);
            produce(pk, es);
            if (++es == GSTAGE) { es = 0; eph ^= 1; }
            pk++;
        }
    }

#pragma unroll
    for (int mt = 0; mt < 4; mt++) {
        int row = m0 + wm + mt * 16 + (lane >> 2);
#pragma unroll
        for (int nt = 0; nt < 4; nt++) {
            int col = n0 + wn + nt * 8 + (lane & 3) * 2;
            float b0 = bias[col], b1 = bias[col + 1];
            float2 v;
            v.x = acc[mt][nt][0] + b0; v.y = acc[mt][nt][1] + b1;
            *(float2*)&C[(size_t)row * N + col] = v;
            v.x = acc[mt][nt][2] + b0; v.y = acc[mt][nt][3] + b1;
            *(float2*)&C[(size_t)(row + 8) * N + col] = v;
        }
    }
}

/* ==== fused prep: RoPE(q)*scale, RoPE(k) head-major + V transpose =======
   grid (SEQ/32, NH), 256 threads. Each block: 32 s-rows of one head.
   V goes through a smem tile (stride 81, odd -> conflict-free both ways). */
__global__ __launch_bounds__(256)
void prep_fused_kernel(const float* __restrict__ qkv, const float* __restrict__ cosb,
                       const float* __restrict__ sinb)
{
    __shared__ uint32_t vt[32 * 81];
    const int tid = threadIdx.x;
    const int h   = blockIdx.y;
    const int s0  = blockIdx.x * 32;

    for (int i = tid; i < 32 * HD; i += 256) {
        int sl = i / HD, d = i - sl * HD;
        int s  = s0 + sl;
        const float* row = qkv + (size_t)s * HID3 + h * HD;
        float c  = cosb[s * HD + d];
        float sn = sinb[s * HD + d];
        size_t dst = ((size_t)h * SEQ + s) * HD + d;

        float xq = row[d];
        float pq = (d < 40) ? row[d + 40] : row[d - 40];
        float vq = (d < 40) ? (xq * c - pq * sn) : (xq * c + pq * sn);
        g_q[dst] = __float_as_uint(vq * ATT_SCALE) + 0x1000u;

        float xk = row[HID + d];
        float pk = (d < 40) ? row[HID + d + 40] : row[HID + d - 40];
        float vk = (d < 40) ? (xk * c - pk * sn) : (xk * c + pk * sn);
        g_k[dst] = __float_as_uint(vk) + 0x1000u;

        vt[sl * 81 + d] = __float_as_uint(row[2 * HID + d]) + 0x1000u;
    }
    __syncthreads();

    for (int i = tid; i < HD * 32; i += 256) {
        int d = i >> 5, sl = i & 31;
        g_vt[((size_t)h * HD + d) * SEQ + s0 + sl] = vt[sl * 81 + d];
    }
}

/* ============== flash attention v5: 512-thread CTA, mbarrier ring ========
   (unchanged from round 16) */
#define A2M 256
#define A2N 64
#define KVP 84
#define VTP 68
#define PPAD 68
#define A3STAGE 3
#define A3S_U32 (A2N * KVP + HD * VTP)
#define SM_KS(s) (sm_u + (s) * A3S_U32)
#define SM_VS(s) (sm_u + (s) * A3S_U32 + A2N * KVP)
#define SM_P     (sm_u + A3STAGE * A3S_U32)
#define ABAR_OFF ((A3STAGE * A3S_U32 + A2M * PPAD) * 4)
#define ATT_SMEM (ABAR_OFF + 64)
#define ATHREADS 512

__global__ __launch_bounds__(ATHREADS, 1)
void attn5_kernel(const uint32_t* __restrict__ gq, const uint32_t* __restrict__ gk,
                  const uint32_t* __restrict__ gvt, uint32_t* __restrict__ outp)
{
    extern __shared__ uint32_t sm_u[];
    const uint32_t sb = (uint32_t)__cvta_generic_to_shared(sm_u);

    const int tid  = threadIdx.x;
    const int lane = tid & 31;
    const int warp = tid >> 5;
    const int qt   = blockIdx.x;
    const int img  = blockIdx.y;
    const int head = blockIdx.z;
    const int sq0  = img * IMG_BLK + qt * A2M;
    const int wq   = warp * 16;
    const int pr   = wq + (lane >> 2);

    const int bfr = ((lane >> 4) & 1) * 8 + (lane & 7);
    const int bfc = ((lane >> 3) & 1) * 4;
    const int afr = wq + ((lane >> 3) & 1) * 8 + (lane & 7);
    const int afc = (lane >> 4) * 4;

    const uint32_t fullb  = sb + ABAR_OFF;
    const uint32_t emptyb = sb + ABAR_OFF + 24;

    if (tid == 0) {
#pragma unroll
        for (int s = 0; s < A3STAGE; s++) {
            mbar_init(fullb  + s * 8, ATHREADS);
            mbar_init(emptyb + s * 8, ATHREADS);
        }
    }
    {
        const uint32_t* src = gq + ((size_t)head * SEQ + sq0) * HD;
        for (int i = tid; i < A2M * (HD / 4); i += ATHREADS) {
            int r = i / (HD / 4), c4 = (i - r * (HD / 4)) * 4;
            *(uint4*)&sm_u[r * KVP + c4] = *(const uint4*)&src[r * HD + c4];
        }
    }
    __syncthreads();

    uint32_t aq[10][4];
#pragma unroll
    for (int ks = 0; ks < 10; ks++) {
        const int c = ks * 8 + (lane & 3);
        aq[ks][0] = sm_u[pr * KVP + c];
        aq[ks][1] = sm_u[(pr + 8) * KVP + c];
        aq[ks][2] = sm_u[pr * KVP + c + 4];
        aq[ks][3] = sm_u[(pr + 8) * KVP + c + 4];
    }
    __syncthreads();

    const uint32_t* kbase  = gk  + ((size_t)head * SEQ + img * IMG_BLK) * HD;
    const uint32_t* vtbase = gvt + (size_t)head * HD * SEQ + img * IMG_BLK;

    auto produce = [&](int jt, int s) {
        const uint32_t* ks_ = kbase + (size_t)jt * A2N * HD;
        uint32_t* kd = SM_KS(s);
        for (int i = tid; i < A2N * (HD / 4); i += ATHREADS) {
            int r = i / (HD / 4), c4 = (i - r * (HD / 4)) * 4;
            cp_async16(&kd[r * KVP + c4], &ks_[r * HD + c4]);
        }
        const uint32_t* vs_ = vtbase + (size_t)jt * A2N;
        uint32_t* vd = SM_VS(s);
        for (int i = tid; i < HD * (A2N / 4); i += ATHREADS) {
            int r = i / (A2N / 4), c4 = (i - r * (A2N / 4)) * 4;
            cp_async16(&vd[r * VTP + c4], &vs_[(size_t)r * SEQ + c4]);
        }
        cpasync_arrive_noinc(fullb + s * 8);
    };

    float o[10][4];
#pragma unroll
    for (int nt = 0; nt < 10; nt++)
#pragma unroll
        for (int r = 0; r < 4; r++) o[nt][r] = 0.f;
    float m0r = -1e30f, m1r = -1e30f, l0 = 0.f, l1 = 0.f;

    const int NT = IMG_BLK / A2N;

    int fs = 0, fph = 0;
    int es = 0, eph = 1;

    for (int pj = 0; pj < 2; pj++) {
        mbar_wait(emptyb + es * 8, eph);
        produce(pj, es);
        if (++es == A3STAGE) { es = 0; eph ^= 1; }
    }
    int pj = 2;

#pragma unroll 1
    for (int jt = 0; jt < NT; jt++) {
        mbar_wait(fullb + fs * 8, fph);

        const uint32_t Kbb = sb + (fs * A3S_U32) * 4;
        const uint32_t Vbb = Kbb + A2N * KVP * 4;

        float sacc[8][4];
#pragma unroll
        for (int nt = 0; nt < 8; nt++)
#pragma unroll
            for (int r = 0; r < 4; r++) sacc[nt][r] = 0.f;

#pragma unroll
        for (int ks = 0; ks < 10; ks++) {
#pragma unroll
            for (int p = 0; p < 4; p++) {
                uint32_t bk[4];
                ldsm_x4(bk, Kbb + (((p * 16 + bfr) * KVP + bfc + ks * 8) << 2));
                mma_tf32(sacc[2 * p],     aq[ks], bk);
                mma_tf32(sacc[2 * p + 1], aq[ks], bk + 2);
            }
        }

        float mx0 = -1e30f, mx1 = -1e30f;
#pragma unroll
        for (int nt = 0; nt < 8; nt++) {
            mx0 = fmaxf(mx0, fmaxf(sacc[nt][0], sacc[nt][1]));
            mx1 = fmaxf(mx1, fmaxf(sacc[nt][2], sacc[nt][3]));
        }
        mx0 = fmaxf(mx0, __shfl_xor_sync(0xffffffffu, mx0, 1));
        mx0 = fmaxf(mx0, __shfl_xor_sync(0xffffffffu, mx0, 2));
        mx1 = fmaxf(mx1, __shfl_xor_sync(0xffffffffu, mx1, 1));
        mx1 = fmaxf(mx1, __shfl_xor_sync(0xffffffffu, mx1, 2));

        float mn0 = fmaxf(m0r, mx0), mn1 = fmaxf(m1r, mx1);
        float cor0 = __expf(m0r - mn0), cor1 = __expf(m1r - mn1);
        m0r = mn0; m1r = mn1;

        uint32_t* Ps = SM_P;
        float rs0 = 0.f, rs1 = 0.f;
#pragma unroll
        for (int nt = 0; nt < 8; nt++) {
            float p0 = __expf(sacc[nt][0] - mn0);
            float p1 = __expf(sacc[nt][1] - mn0);
            float p2 = __expf(sacc[nt][2] - mn1);
            float p3 = __expf(sacc[nt][3] - mn1);
            rs0 += p0 + p1;  rs1 += p2 + p3;
            int col = nt * 8 + (lane & 3) * 2;
            uint2 u01 = { __float_as_uint(p0) + 0x1000u, __float_as_uint(p1) + 0x1000u };
            *(uint2*)&Ps[pr * PPAD + col] = u01;
            uint2 u23 = { __float_as_uint(p2) + 0x1000u, __float_as_uint(p3) + 0x1000u };
            *(uint2*)&Ps[(pr + 8) * PPAD + col] = u23;
        }
        rs0 += __shfl_xor_sync(0xffffffffu, rs0, 1);
        rs0 += __shfl_xor_sync(0xffffffffu, rs0, 2);
        rs1 += __shfl_xor_sync(0xffffffffu, rs1, 1);
        rs1 += __shfl_xor_sync(0xffffffffu, rs1, 2);
        l0 = l0 * cor0 + rs0;
        l1 = l1 * cor1 + rs1;
#pragma unroll
        for (int nt = 0; nt < 10; nt++) {
            o[nt][0] *= cor0; o[nt][1] *= cor0;
            o[nt][2] *= cor1; o[nt][3] *= cor1;
        }

        __syncwarp();

        const uint32_t Pbb = sb + (A3STAGE * A3S_U32) * 4;
#pragma unroll
        for (int ks = 0; ks < 8; ks++) {
            uint32_t ap[4];
            ldsm_x4(ap, Pbb + ((afr * PPAD + afc + ks * 8) << 2));
#pragma unroll
            for (int p = 0; p < 5; p++) {
                uint32_t bv[4];
                ldsm_x4(bv, Vbb + (((p * 16 + bfr) * VTP + bfc + ks * 8) << 2));
                mma_tf32(o[2 * p],     ap, bv);
                mma_tf32(o[2 * p + 1], ap, bv + 2);
            }
        }
        __syncwarp();

        mbar_arrive(emptyb + fs * 8);
        if (++fs == A3STAGE) { fs = 0; fph ^= 1; }

        if (pj < NT) {
            mbar_wait(emptyb + es * 8, eph);
            produce(pj, es);
            if (++es == A3STAGE) { es = 0; eph ^= 1; }
            pj++;
        }
    }

    float inv0 = 1.0f / l0, inv1 = 1.0f / l1;
    int srow = sq0 + pr;
#pragma unroll
    for (int nt = 0; nt < 10; nt++) {
        int col = head * HD + nt * 8 + (lane & 3) * 2;
        uint2 v0 = { __float_as_uint(o[nt][0] * inv0) + 0x1000u,
                     __float_as_uint(o[nt][1] * inv0) + 0x1000u };
        *(uint2*)&outp[(size_t)srow * HID + col] = v0;
        uint2 v1 = { __float_as_uint(o[nt][2] * inv1) + 0x1000u,
                     __float_as_uint(o[nt][3] * inv1) + 0x1000u };
        *(uint2*)&outp[(size_t)(srow + 8) * HID + col] = v1;
    }
}

/* ============================== launch =================================== */
extern "C" void kernel_launch(void* const* d_in, const int* in_sizes, int n_in,
                              void* d_out, int out_size)
{
    (void)in_sizes; (void)n_in; (void)out_size;
    const float* hidden = (const float*)d_in[0];
    const float* cosb   = (const float*)d_in[2];
    const float* sinb   = (const float*)d_in[3];
    const float* qkv_w  = (const float*)d_in[4];
    const float* qkv_b  = (const float*)d_in[5];
    const float* proj_w = (const float*)d_in[6];
    const float* proj_b = (const float*)d_in[7];
    float* out = (float*)d_out;

    float *qkv_ptr;
    uint32_t *att_ptr, *qp, *kp, *vtp, *hid_r, *wq_r, *wp_r;
    cudaGetSymbolAddress((void**)&qkv_ptr, g_qkv);
    cudaGetSymbolAddress((void**)&att_ptr, g_att);
    cudaGetSymbolAddress((void**)&qp, g_q);
    cudaGetSymbolAddress((void**)&kp, g_k);
    cudaGetSymbolAddress((void**)&vtp, g_vt);
    cudaGetSymbolAddress((void**)&hid_r, g_hid_r);
    cudaGetSymbolAddress((void**)&wq_r, g_wq_r);
    cudaGetSymbolAddress((void**)&wp_r, g_wp_r);

    cudaFuncSetAttribute(gemm_bias_kernel, cudaFuncAttributeMaxDynamicSharedMemorySize,
                         GEMM_SMEM);
    cudaFuncSetAttribute(attn5_kernel, cudaFuncAttributeMaxDynamicSharedMemorySize,
                         ATT_SMEM);

    /* pre-round all operands (tf32 RN) in one launch */
    round_all_kernel<<<(RN3 + 255) / 256, 256>>>((const uint32_t*)hidden,
                                                 (const uint32_t*)qkv_w,
                                                 (const uint32_t*)proj_w,
                                                 hid_r, wq_r, wp_r);

    dim3 g1(HID3 / GBN, SEQ / GBM);
    gemm_bias_kernel<<<g1, 256, GEMM_SMEM>>>(hid_r, wq_r, qkv_b, qkv_ptr,
                                             SEQ, HID3, HID);

    dim3 gp(SEQ / 32, NH);
    prep_fused_kernel<<<gp, 256>>>(qkv_ptr, cosb, sinb);

    dim3 ga(IMG_BLK / A2M, 4, NH);
    attn5_kernel<<<ga, ATHREADS, ATT_SMEM>>>(qp, kp, vtp, att_ptr);

    dim3 g3(HID / GBN, SEQ / GBM);
    gemm_bias_kernel<<<g3, 256, GEMM_SMEM>>>(att_ptr, wp_r, proj_b, out,
                                             SEQ, HID, HID);
}